// round 13
// baseline (speedup 1.0000x reference)
#include <cuda_runtime.h>

#define NN 20000
#define EE 100000
#define FNF 92
#define FEF 50
#define DD 64
#define GG 128
#define LL 3
#define YW 4160    // 64*64 + 64 bias cols (Y row stride, logical)
#define W2W 4352   // w2t row stride, padded so B tile loads never go OOB

// ---------------- device scratch (static; no runtime allocation) ----------------
__device__ float  g_h[NN * DD];
__device__ float  g_hid[(size_t)EE * DD];
__device__ float  g_agg[NN * DD];
__device__ float  g_m[NN * DD];
__device__ float  g_cnt[NN];
__device__ double g_bnsum[DD];
__device__ double g_bnsq[DD];
__device__ float  g_mu[DD];
__device__ float  g_rstd[DD];
__device__ float  g_pool[GG * DD];
__device__ float  g_pcnt[GG];
__device__ float  g_Y[(size_t)NN * YW];
__device__ float  g_w2t[64 * W2W];
__device__ float  g_wihT[DD * 192];   // [d][gate*64 + out]
__device__ float  g_whhT[DD * 192];
__device__ int    g_deg[NN];
__device__ int    g_off[NN];
__device__ int    g_rank[EE];
__device__ int    g_eorder[EE];

// ---------------- init / CSR build ----------------
__global__ void k_init() {
    int i = blockIdx.x * blockDim.x + threadIdx.x;
    if (i < NN) { g_cnt[i] = 0.f; g_deg[i] = 0; }
    if (i < GG * DD) g_pool[i] = 0.f;
    if (i < GG) g_pcnt[i] = 0.f;
}

__global__ void k_deg(const int* __restrict__ src, const int* __restrict__ dst,
                      const int* __restrict__ batch) {
    int i = blockIdx.x * blockDim.x + threadIdx.x;
    if (i < EE) {
        g_rank[i] = atomicAdd(&g_deg[src[i]], 1);
        atomicAdd(&g_cnt[dst[i]], 1.f);
    }
    if (i < NN) atomicAdd(&g_pcnt[batch[i]], 1.f);
}

__global__ void k_scan() {
    __shared__ int s[1024];
    __shared__ int carry;
    int tid = threadIdx.x;
    if (tid == 0) carry = 0;
    __syncthreads();
    for (int base = 0; base < NN; base += 1024) {
        int v = (base + tid < NN) ? g_deg[base + tid] : 0;
        s[tid] = v;
        __syncthreads();
        for (int off = 1; off < 1024; off <<= 1) {
            int t = (tid >= off) ? s[tid - off] : 0;
            __syncthreads();
            s[tid] += t;
            __syncthreads();
        }
        if (base + tid < NN) g_off[base + tid] = carry + s[tid] - v;
        __syncthreads();
        if (tid == 0) carry += s[1023];
        __syncthreads();
    }
}

__global__ void k_perm(const int* __restrict__ src) {
    int e = blockIdx.x * blockDim.x + threadIdx.x;
    if (e < EE) g_eorder[g_off[src[e]] + g_rank[e]] = e;
}

// ---------------- per-layer prep: zero agg/bn + W2 transpose + GRU W transpose ----------------
#define PREP_ZL   (NN * DD)
#define PREP_W2T  (64 * W2W)
#define PREP_WTR  (DD * 192)
#define PREP_TOT  (PREP_ZL + PREP_W2T + PREP_WTR)
__global__ void k_prep(const float* __restrict__ W2, const float* __restrict__ b2,
                       const float* __restrict__ wih, const float* __restrict__ whh) {
    int i = blockIdx.x * blockDim.x + threadIdx.x;
    if (i < DD) { g_bnsum[i] = 0.0; g_bnsq[i] = 0.0; }
    if (i < PREP_ZL) {
        g_agg[i] = 0.f;
    } else if (i < PREP_ZL + PREP_W2T) {
        int t = i - PREP_ZL;
        int r = t / W2W, col = t % W2W;
        float v;
        if (col < 4096) {
            int j = col >> 6, o = col & 63;
            v = W2[j * 4096 + r * 64 + o];
        } else if (col < YW) {
            v = b2[r * 64 + (col - 4096)];
        } else {
            v = 0.f;   // read-side pad, never stored to Y
        }
        g_w2t[t] = v;
    } else if (i < PREP_TOT) {
        int t = i - PREP_ZL - PREP_W2T;
        int d = t / 192, k = t % 192;
        g_wihT[t] = wih[k * DD + d];
        g_whhT[t] = whh[k * DD + d];
    }
}

// ---------------- pre-FC ----------------
__global__ void k_pre(const float* __restrict__ x, const float* __restrict__ w,
                      const float* __restrict__ b) {
    __shared__ float xs[4][FNF];
    int tx = threadIdx.x, ty = threadIdx.y;
    int n = blockIdx.x * 4 + ty;
    for (int f = tx; f < FNF; f += 64) xs[ty][f] = x[(size_t)n * FNF + f];
    __syncthreads();
    float acc = b[tx];
#pragma unroll
    for (int f = 0; f < FNF; ++f) acc += xs[ty][f] * w[f * DD + tx];
    g_h[n * DD + tx] = fmaxf(acc, 0.f);
}

// ---------------- edge MLP stage 1 ----------------
__global__ void k_hid(const float* __restrict__ ea, const float* __restrict__ w,
                      const float* __restrict__ b) {
    __shared__ float es[4][FEF];
    int tx = threadIdx.x, ty = threadIdx.y;
    int e = blockIdx.x * 4 + ty;
    for (int f = tx; f < FEF; f += 64) es[ty][f] = ea[(size_t)e * FEF + f];
    __syncthreads();
    float acc = b[tx];
#pragma unroll
    for (int f = 0; f < FEF; ++f) acc += es[ty][f] * w[f * DD + tx];
    g_hid[(size_t)e * DD + tx] = fmaxf(acc, 0.f);
}

// ---------------- Y GEMM: g_Y = g_h @ g_w2t, B staged via smem (R11 version) ----------------
__global__ void __launch_bounds__(256, 2) k_ygemm() {
    __shared__ __align__(16) float hsT[64][68];
    __shared__ __align__(16) float Bs[16][256];
    int tid = threadIdx.x;
    int mb = blockIdx.x * 64;
    int nb = blockIdx.y * 256;

    for (int t = tid; t < 1024; t += 256) {
        int m = t >> 4, q = t & 15;
        int gm = mb + m;
        float4 v = make_float4(0.f, 0.f, 0.f, 0.f);
        if (gm < NN) v = *(const float4*)&g_h[gm * DD + q * 4];
        hsT[q * 4 + 0][m] = v.x; hsT[q * 4 + 1][m] = v.y;
        hsT[q * 4 + 2][m] = v.z; hsT[q * 4 + 3][m] = v.w;
    }

    int mg = tid >> 5, ng = tid & 31;
    int m0 = mg * 8;
    int nl0 = (ng & 15) * 4 + (ng >> 4) * 128;

    int bf_row[4], bf_col[4];
#pragma unroll
    for (int i = 0; i < 4; i++) {
        int f4 = tid + i * 256;
        bf_row[i] = f4 >> 6;
        bf_col[i] = (f4 & 63) * 4;
    }

    float4 pre[4];
#pragma unroll
    for (int i = 0; i < 4; i++)
        pre[i] = *(const float4*)&g_w2t[(size_t)bf_row[i] * W2W + nb + bf_col[i]];
#pragma unroll
    for (int i = 0; i < 4; i++)
        *(float4*)&Bs[bf_row[i]][bf_col[i]] = pre[i];
    __syncthreads();

    float acc[8][8];
#pragma unroll
    for (int a = 0; a < 8; a++)
#pragma unroll
        for (int b = 0; b < 8; b++) acc[a][b] = 0.f;

#pragma unroll
    for (int c = 0; c < 4; c++) {
        if (c < 3) {
#pragma unroll
            for (int i = 0; i < 4; i++)
                pre[i] = *(const float4*)&g_w2t[(size_t)((c + 1) * 16 + bf_row[i]) * W2W + nb + bf_col[i]];
        }
#pragma unroll
        for (int kk = 0; kk < 16; kk++) {
            int k = c * 16 + kk;
            float4 a0 = *(const float4*)&hsT[k][m0];
            float4 a1 = *(const float4*)&hsT[k][m0 + 4];
            float4 b0 = *(const float4*)&Bs[kk][nl0];
            float4 b1 = *(const float4*)&Bs[kk][nl0 + 64];
            float av[8] = {a0.x, a0.y, a0.z, a0.w, a1.x, a1.y, a1.z, a1.w};
            float bv[8] = {b0.x, b0.y, b0.z, b0.w, b1.x, b1.y, b1.z, b1.w};
#pragma unroll
            for (int mm = 0; mm < 8; mm++)
#pragma unroll
                for (int nn = 0; nn < 8; nn++) acc[mm][nn] += av[mm] * bv[nn];
        }
        __syncthreads();
        if (c < 3) {
#pragma unroll
            for (int i = 0; i < 4; i++)
                *(float4*)&Bs[bf_row[i]][bf_col[i]] = pre[i];
            __syncthreads();
        }
    }

    bool v0 = (nb + nl0) < YW;
    bool v1 = (nb + nl0 + 64) < YW;
#pragma unroll
    for (int mm = 0; mm < 8; mm++) {
        int gm = mb + m0 + mm;
        if (gm >= NN) continue;
        float* Cp = g_Y + (size_t)gm * YW + nb + nl0;
        if (v0) *(float4*)Cp        = make_float4(acc[mm][0], acc[mm][1], acc[mm][2], acc[mm][3]);
        if (v1) *(float4*)(Cp + 64) = make_float4(acc[mm][4], acc[mm][5], acc[mm][6], acc[mm][7]);
    }
}

// ---------------- edge phase v2: block per src node, Y row staged in smem ----------------
// msg[e,o] = bias[o] + sum_j hid[e,j]*Ys[j*64+o]; each thread: 4 edges x 4 outputs,
// so each Ys LDS.128 is amortized over 4 edges.
__global__ void __launch_bounds__(256) k_edge(const int* __restrict__ dst) {
    int n = blockIdx.x;
    int dg = g_deg[n];
    if (dg == 0) return;
    int d0 = g_off[n];
    __shared__ __align__(16) float Ys[YW];         // 16.6 KB
    __shared__ __align__(16) float hid_s[64][64];  // 16 KB
    __shared__ int sdst[64];
    int tid = threadIdx.x;

    for (int t = tid; t < YW / 4; t += 256)
        *(float4*)&Ys[t * 4] = *(const float4*)&g_Y[(size_t)n * YW + t * 4];

    int w = tid >> 5, lane = tid & 31;
    int e0l = w * 8 + (lane >> 4) * 4;   // this thread's first edge slot (0..60)
    int o4 = (lane & 15) * 4;

    for (int base = 0; base < dg; base += 64) {
        int ne = min(64, dg - base);
        __syncthreads();   // Ys ready (1st iter) / previous chunk done
        for (int t = tid; t < ne * 16; t += 256) {
            int el = t >> 4, q = t & 15;
            int eo = g_eorder[d0 + base + el];
            *(float4*)&hid_s[el][q * 4] = *(const float4*)&g_hid[(size_t)eo * DD + q * 4];
        }
        if (tid < ne) sdst[tid] = dst[g_eorder[d0 + base + tid]];
        __syncthreads();

        if (e0l < ne) {
            int ecnt = min(4, ne - e0l);
            float4 acc[4];
#pragma unroll
            for (int e = 0; e < 4; e++) acc[e] = make_float4(0.f, 0.f, 0.f, 0.f);
#pragma unroll 8
            for (int j = 0; j < 64; j++) {
                float4 y = *(const float4*)&Ys[j * 64 + o4];
#pragma unroll
                for (int e = 0; e < 4; e++) {
                    float hj = hid_s[e0l + e][j];
                    acc[e].x += hj * y.x; acc[e].y += hj * y.y;
                    acc[e].z += hj * y.z; acc[e].w += hj * y.w;
                }
            }
            float4 bias = *(const float4*)&Ys[4096 + o4];
            for (int e = 0; e < ecnt; e++) {
                float* ap = &g_agg[sdst[e0l + e] * DD + o4];
                atomicAdd(ap + 0, acc[e].x + bias.x);
                atomicAdd(ap + 1, acc[e].y + bias.y);
                atomicAdd(ap + 2, acc[e].z + bias.z);
                atomicAdd(ap + 3, acc[e].w + bias.w);
            }
        }
    }
}

// ---------------- conv combine + BN stats ----------------
__global__ void k_bn1(const float* __restrict__ root, const float* __restrict__ cb) {
    __shared__ float hs[4][DD];
    __shared__ float ms[4][DD];
    int tx = threadIdx.x, ty = threadIdx.y;
    int n = blockIdx.x * 4 + ty;
    hs[ty][tx] = g_h[n * DD + tx];
    __syncthreads();
    float c = g_cnt[n];
    float acc = g_agg[n * DD + tx] / fmaxf(c, 1.f) + cb[tx];
#pragma unroll
    for (int d = 0; d < DD; ++d) acc += hs[ty][d] * root[d * DD + tx];
    g_m[n * DD + tx] = acc;
    ms[ty][tx] = acc;
    __syncthreads();
    if (ty == 0) {
        float s  = ms[0][tx] + ms[1][tx] + ms[2][tx] + ms[3][tx];
        float sq = ms[0][tx] * ms[0][tx] + ms[1][tx] * ms[1][tx] +
                   ms[2][tx] * ms[2][tx] + ms[3][tx] * ms[3][tx];
        atomicAdd(&g_bnsum[tx], (double)s);
        atomicAdd(&g_bnsq[tx], (double)sq);
    }
}

__global__ void k_bnfin() {
    int o = threadIdx.x;
    double mu = g_bnsum[o] / (double)NN;
    double var = g_bnsq[o] / (double)NN - mu * mu;
    g_mu[o] = (float)mu;
    g_rstd[o] = rsqrtf((float)var + 1e-5f);
}

// ---------------- BN-apply + relu + GRU, 4 nodes/thread ----------------
__global__ void __launch_bounds__(256) k_gru(const float* __restrict__ gamma,
                                             const float* __restrict__ beta,
                                             const float* __restrict__ bih,
                                             const float* __restrict__ bhh) {
    __shared__ float ms[16][DD];
    __shared__ float hs[16][DD];
    int tx = threadIdx.x, ty = threadIdx.y;
    int tid = ty * 64 + tx;
    int nb = blockIdx.x * 16;
    for (int t = tid; t < 1024; t += 256) {
        int i = t >> 6, d = t & 63;
        int n = nb + i;
        float mv = g_m[n * DD + d];
        mv = gamma[d] * (mv - g_mu[d]) * g_rstd[d] + beta[d];
        ms[i][d] = fmaxf(mv, 0.f);
        hs[i][d] = g_h[n * DD + d];
    }
    __syncthreads();
    float gr[4], gz[4], gn[4], hr[4], hz[4], hn[4];
    float b0 = bih[tx], b1 = bih[DD + tx], b2 = bih[2 * DD + tx];
    float c0 = bhh[tx], c1 = bhh[DD + tx], c2 = bhh[2 * DD + tx];
#pragma unroll
    for (int r = 0; r < 4; r++) {
        gr[r] = b0; gz[r] = b1; gn[r] = b2;
        hr[r] = c0; hz[r] = c1; hn[r] = c2;
    }
    int i0 = ty * 4;
#pragma unroll 4
    for (int d = 0; d < DD; ++d) {
        const float* wT = g_wihT + d * 192;
        const float* vT = g_whhT + d * 192;
        float w0 = wT[tx], w1 = wT[64 + tx], w2 = wT[128 + tx];
        float v0 = vT[tx], v1 = vT[64 + tx], v2 = vT[128 + tx];
#pragma unroll
        for (int r = 0; r < 4; r++) {
            float md = ms[i0 + r][d], hd = hs[i0 + r][d];
            gr[r] += md * w0; gz[r] += md * w1; gn[r] += md * w2;
            hr[r] += hd * v0; hz[r] += hd * v1; hn[r] += hd * v2;
        }
    }
#pragma unroll
    for (int r = 0; r < 4; r++) {
        int n = nb + i0 + r;
        float hvv = hs[i0 + r][tx];
        float rr = 1.f / (1.f + __expf(-(gr[r] + hr[r])));
        float zz = 1.f / (1.f + __expf(-(gz[r] + hz[r])));
        float nn2 = tanhf(gn[r] + rr * hn[r]);
        g_h[n * DD + tx] = (1.f - zz) * nn2 + zz * hvv;
    }
}

// ---------------- pooling + head ----------------
__global__ void k_pool(const int* __restrict__ batch) {
    int i = blockIdx.x * blockDim.x + threadIdx.x;
    if (i >= NN * DD) return;
    int n = i >> 6, o = i & 63;
    atomicAdd(&g_pool[batch[n] * DD + o], g_h[i]);
}

__global__ void k_head(const float* __restrict__ pw, const float* __restrict__ pb,
                       const float* __restrict__ ow, const float* __restrict__ ob,
                       float* __restrict__ out) {
    __shared__ float p[DD];
    __shared__ float q[DD];
    int g = blockIdx.x, o = threadIdx.x;
    p[o] = g_pool[g * DD + o] / fmaxf(g_pcnt[g], 1.f);
    __syncthreads();
    float acc = pb[o];
#pragma unroll
    for (int d = 0; d < DD; ++d) acc += p[d] * pw[d * DD + o];
    q[o] = fmaxf(acc, 0.f) * ow[o];
    __syncthreads();
    if (o == 0) {
        float s = ob[0];
        for (int d = 0; d < DD; ++d) s += q[d];
        out[g] = s;
    }
}

// ---------------- launch ----------------
extern "C" void kernel_launch(void* const* d_in, const int* in_sizes, int n_in,
                              void* d_out, int out_size) {
    const float* x     = (const float*)d_in[0];
    const int*   ei    = (const int*)d_in[1];
    const float* ea    = (const float*)d_in[2];
    const int*   batch = (const int*)d_in[3];
    const float* pre_w = (const float*)d_in[4];
    const float* pre_b = (const float*)d_in[5];
    const float* ew1   = (const float*)d_in[6];
    const float* eb1   = (const float*)d_in[7];
    const float* ew2   = (const float*)d_in[8];
    const float* eb2   = (const float*)d_in[9];
    const float* root  = (const float*)d_in[10];
    const float* cb    = (const float*)d_in[11];
    const float* bng   = (const float*)d_in[12];
    const float* bnb   = (const float*)d_in[13];
    const float* wih   = (const float*)d_in[14];
    const float* whh   = (const float*)d_in[15];
    const float* bih   = (const float*)d_in[16];
    const float* bhh   = (const float*)d_in[17];
    const float* pw    = (const float*)d_in[18];
    const float* pb    = (const float*)d_in[19];
    const float* ow    = (const float*)d_in[20];
    const float* ob    = (const float*)d_in[21];
    float* out = (float*)d_out;
    const int* src = ei;
    const int* dst = ei + EE;

    // ncu captures the 4th launch (index 3): keep layer-0 k_ygemm there (control).
    k_pre<<<NN / 4, dim3(64, 4)>>>(x, pre_w, pre_b);                   // 0
    k_prep<<<(PREP_TOT + 255) / 256, 256>>>(ew2, eb2, wih, whh);       // 1 (layer 0)
    k_init<<<(NN + 255) / 256, 256>>>();                               // 2
    k_ygemm<<<dim3((NN + 63) / 64, (YW + 255) / 256), 256>>>();        // 3 (layer 0) <- profiled
    k_deg<<<(EE + 255) / 256, 256>>>(src, dst, batch);                 // 4
    k_scan<<<1, 1024>>>();                                             // 5
    k_perm<<<(EE + 255) / 256, 256>>>(src);                            // 6
    k_hid<<<EE / 4, dim3(64, 4)>>>(ea, ew1, eb1);                      // 7 (layer 0)

    for (int l = 0; l < LL; l++) {
        if (l > 0) {
            k_prep<<<(PREP_TOT + 255) / 256, 256>>>(ew2 + (size_t)l * DD * DD * DD,
                                                    eb2 + (size_t)l * DD * DD,
                                                    wih + (size_t)l * 3 * DD * DD,
                                                    whh + (size_t)l * 3 * DD * DD);
            k_hid<<<EE / 4, dim3(64, 4)>>>(ea, ew1 + (size_t)l * FEF * DD, eb1 + l * DD);
            k_ygemm<<<dim3((NN + 63) / 64, (YW + 255) / 256), 256>>>();
        }
        k_edge<<<NN, 256>>>(dst);
        k_bn1<<<NN / 4, dim3(64, 4)>>>(root + (size_t)l * DD * DD, cb + l * DD);
        k_bnfin<<<1, 64>>>();
        k_gru<<<NN / 16, dim3(64, 4)>>>(bng + l * DD, bnb + l * DD,
                                        bih + (size_t)l * 3 * DD,
                                        bhh + (size_t)l * 3 * DD);
    }

    k_pool<<<(NN * DD + 255) / 256, 256>>>(batch);
    k_head<<<GG, 64>>>(pw, pb, ow, ob, out);
}

// round 14
// speedup vs baseline: 1.1808x; 1.1808x over previous
#include <cuda_runtime.h>

#define NN 20000
#define EE 100000
#define FNF 92
#define FEF 50
#define DD 64
#define GG 128
#define LL 3
#define YW 4160    // 64*64 + 64 bias cols (Y row stride, logical)
#define W2W 4352   // w2t row stride, padded so B tile loads never go OOB

// ---------------- device scratch (static; no runtime allocation) ----------------
__device__ float  g_h[NN * DD];
__device__ float  g_hid[(size_t)EE * DD];
__device__ float  g_agg[NN * DD];
__device__ float  g_m[NN * DD];
__device__ float  g_cnt[NN];
__device__ double g_bnsum[DD];
__device__ double g_bnsq[DD];
__device__ float  g_mu[DD];
__device__ float  g_rstd[DD];
__device__ float  g_pool[GG * DD];
__device__ float  g_pcnt[GG];
__device__ float  g_Y[(size_t)NN * YW];
__device__ float  g_w2t[64 * W2W];
__device__ float  g_wihT[DD * 192];   // [d][gate*64 + out]
__device__ float  g_whhT[DD * 192];
__device__ int    g_deg[NN];
__device__ int    g_off[NN];
__device__ int    g_rank[EE];
__device__ int    g_eorder[EE];

// ---------------- init / CSR build ----------------
__global__ void k_init() {
    int i = blockIdx.x * blockDim.x + threadIdx.x;
    if (i < NN) { g_cnt[i] = 0.f; g_deg[i] = 0; }
    if (i < GG * DD) g_pool[i] = 0.f;
    if (i < GG) g_pcnt[i] = 0.f;
}

__global__ void k_deg(const int* __restrict__ src, const int* __restrict__ dst,
                      const int* __restrict__ batch) {
    int i = blockIdx.x * blockDim.x + threadIdx.x;
    if (i < EE) {
        g_rank[i] = atomicAdd(&g_deg[src[i]], 1);
        atomicAdd(&g_cnt[dst[i]], 1.f);
    }
    if (i < NN) atomicAdd(&g_pcnt[batch[i]], 1.f);
}

__global__ void k_scan() {
    __shared__ int s[1024];
    __shared__ int carry;
    int tid = threadIdx.x;
    if (tid == 0) carry = 0;
    __syncthreads();
    for (int base = 0; base < NN; base += 1024) {
        int v = (base + tid < NN) ? g_deg[base + tid] : 0;
        s[tid] = v;
        __syncthreads();
        for (int off = 1; off < 1024; off <<= 1) {
            int t = (tid >= off) ? s[tid - off] : 0;
            __syncthreads();
            s[tid] += t;
            __syncthreads();
        }
        if (base + tid < NN) g_off[base + tid] = carry + s[tid] - v;
        __syncthreads();
        if (tid == 0) carry += s[1023];
        __syncthreads();
    }
}

__global__ void k_perm(const int* __restrict__ src) {
    int e = blockIdx.x * blockDim.x + threadIdx.x;
    if (e < EE) g_eorder[g_off[src[e]] + g_rank[e]] = e;
}

// ---------------- per-layer prep: zero agg/bn + W2 transpose + GRU W transpose ----------------
#define PREP_ZL   (NN * DD)
#define PREP_W2T  (64 * W2W)
#define PREP_WTR  (DD * 192)
#define PREP_TOT  (PREP_ZL + PREP_W2T + PREP_WTR)
__global__ void k_prep(const float* __restrict__ W2, const float* __restrict__ b2,
                       const float* __restrict__ wih, const float* __restrict__ whh) {
    int i = blockIdx.x * blockDim.x + threadIdx.x;
    if (i < DD) { g_bnsum[i] = 0.0; g_bnsq[i] = 0.0; }
    if (i < PREP_ZL) {
        g_agg[i] = 0.f;
    } else if (i < PREP_ZL + PREP_W2T) {
        int t = i - PREP_ZL;
        int r = t / W2W, col = t % W2W;
        float v;
        if (col < 4096) {
            int j = col >> 6, o = col & 63;
            v = W2[j * 4096 + r * 64 + o];
        } else if (col < YW) {
            v = b2[r * 64 + (col - 4096)];
        } else {
            v = 0.f;   // read-side pad, never stored to Y
        }
        g_w2t[t] = v;
    } else if (i < PREP_TOT) {
        int t = i - PREP_ZL - PREP_W2T;
        int d = t / 192, k = t % 192;
        g_wihT[t] = wih[k * DD + d];
        g_whhT[t] = whh[k * DD + d];
    }
}

// ---------------- pre-FC ----------------
__global__ void k_pre(const float* __restrict__ x, const float* __restrict__ w,
                      const float* __restrict__ b) {
    __shared__ float xs[4][FNF];
    int tx = threadIdx.x, ty = threadIdx.y;
    int n = blockIdx.x * 4 + ty;
    for (int f = tx; f < FNF; f += 64) xs[ty][f] = x[(size_t)n * FNF + f];
    __syncthreads();
    float acc = b[tx];
#pragma unroll
    for (int f = 0; f < FNF; ++f) acc += xs[ty][f] * w[f * DD + tx];
    g_h[n * DD + tx] = fmaxf(acc, 0.f);
}

// ---------------- edge MLP stage 1 ----------------
__global__ void k_hid(const float* __restrict__ ea, const float* __restrict__ w,
                      const float* __restrict__ b) {
    __shared__ float es[4][FEF];
    int tx = threadIdx.x, ty = threadIdx.y;
    int e = blockIdx.x * 4 + ty;
    for (int f = tx; f < FEF; f += 64) es[ty][f] = ea[(size_t)e * FEF + f];
    __syncthreads();
    float acc = b[tx];
#pragma unroll
    for (int f = 0; f < FEF; ++f) acc += es[ty][f] * w[f * DD + tx];
    g_hid[(size_t)e * DD + tx] = fmaxf(acc, 0.f);
}

// ---------------- Y GEMM: g_Y = g_h @ g_w2t, B staged via smem (R11 version) ----------------
__global__ void __launch_bounds__(256, 2) k_ygemm() {
    __shared__ __align__(16) float hsT[64][68];
    __shared__ __align__(16) float Bs[16][256];
    int tid = threadIdx.x;
    int mb = blockIdx.x * 64;
    int nb = blockIdx.y * 256;

    for (int t = tid; t < 1024; t += 256) {
        int m = t >> 4, q = t & 15;
        int gm = mb + m;
        float4 v = make_float4(0.f, 0.f, 0.f, 0.f);
        if (gm < NN) v = *(const float4*)&g_h[gm * DD + q * 4];
        hsT[q * 4 + 0][m] = v.x; hsT[q * 4 + 1][m] = v.y;
        hsT[q * 4 + 2][m] = v.z; hsT[q * 4 + 3][m] = v.w;
    }

    int mg = tid >> 5, ng = tid & 31;
    int m0 = mg * 8;
    int nl0 = (ng & 15) * 4 + (ng >> 4) * 128;

    int bf_row[4], bf_col[4];
#pragma unroll
    for (int i = 0; i < 4; i++) {
        int f4 = tid + i * 256;
        bf_row[i] = f4 >> 6;
        bf_col[i] = (f4 & 63) * 4;
    }

    float4 pre[4];
#pragma unroll
    for (int i = 0; i < 4; i++)
        pre[i] = *(const float4*)&g_w2t[(size_t)bf_row[i] * W2W + nb + bf_col[i]];
#pragma unroll
    for (int i = 0; i < 4; i++)
        *(float4*)&Bs[bf_row[i]][bf_col[i]] = pre[i];
    __syncthreads();

    float acc[8][8];
#pragma unroll
    for (int a = 0; a < 8; a++)
#pragma unroll
        for (int b = 0; b < 8; b++) acc[a][b] = 0.f;

#pragma unroll
    for (int c = 0; c < 4; c++) {
        if (c < 3) {
#pragma unroll
            for (int i = 0; i < 4; i++)
                pre[i] = *(const float4*)&g_w2t[(size_t)((c + 1) * 16 + bf_row[i]) * W2W + nb + bf_col[i]];
        }
#pragma unroll
        for (int kk = 0; kk < 16; kk++) {
            int k = c * 16 + kk;
            float4 a0 = *(const float4*)&hsT[k][m0];
            float4 a1 = *(const float4*)&hsT[k][m0 + 4];
            float4 b0 = *(const float4*)&Bs[kk][nl0];
            float4 b1 = *(const float4*)&Bs[kk][nl0 + 64];
            float av[8] = {a0.x, a0.y, a0.z, a0.w, a1.x, a1.y, a1.z, a1.w};
            float bv[8] = {b0.x, b0.y, b0.z, b0.w, b1.x, b1.y, b1.z, b1.w};
#pragma unroll
            for (int mm = 0; mm < 8; mm++)
#pragma unroll
                for (int nn = 0; nn < 8; nn++) acc[mm][nn] += av[mm] * bv[nn];
        }
        __syncthreads();
        if (c < 3) {
#pragma unroll
            for (int i = 0; i < 4; i++)
                *(float4*)&Bs[bf_row[i]][bf_col[i]] = pre[i];
            __syncthreads();
        }
    }

    bool v0 = (nb + nl0) < YW;
    bool v1 = (nb + nl0 + 64) < YW;
#pragma unroll
    for (int mm = 0; mm < 8; mm++) {
        int gm = mb + m0 + mm;
        if (gm >= NN) continue;
        float* Cp = g_Y + (size_t)gm * YW + nb + nl0;
        if (v0) *(float4*)Cp        = make_float4(acc[mm][0], acc[mm][1], acc[mm][2], acc[mm][3]);
        if (v1) *(float4*)(Cp + 64) = make_float4(acc[mm][4], acc[mm][5], acc[mm][6], acc[mm][7]);
    }
}

// ---------------- edge phase (R11 version): 32 src-grouped edges/block ----------------
__global__ void __launch_bounds__(256) k_edge(const int* __restrict__ src,
                                              const int* __restrict__ dst) {
    __shared__ float hid_s[32][64];
    __shared__ int ssrc[32], sdst[32], seo[32];
    int tid = threadIdx.x;
    int eb0 = blockIdx.x * 32;
    if (tid < 32) {
        int eo = g_eorder[eb0 + tid];
        seo[tid] = eo;
        ssrc[tid] = src[eo];
        sdst[tid] = dst[eo];
    }
    __syncthreads();
    for (int t = tid; t < 32 * 16; t += 256) {
        int el = t >> 4, q = t & 15;
        *(float4*)&hid_s[el][q * 4] = *(const float4*)&g_hid[(size_t)seo[el] * DD + q * 4];
    }
    __syncthreads();
    int o4 = (tid & 15) * 4;
    int el0 = tid >> 4;
#pragma unroll
    for (int m = 0; m < 2; m++) {
        int el = el0 + 16 * m;
        const float* Yr = g_Y + (size_t)ssrc[el] * YW;
        float4 acc = *(const float4*)&Yr[4096 + o4];
#pragma unroll 8
        for (int j = 0; j < 64; j++) {
            float hj = hid_s[el][j];
            float4 yv = *(const float4*)&Yr[j * 64 + o4];
            acc.x += hj * yv.x; acc.y += hj * yv.y;
            acc.z += hj * yv.z; acc.w += hj * yv.w;
        }
        float* ap = g_agg + (size_t)sdst[el] * DD + o4;
        atomicAdd(ap + 0, acc.x); atomicAdd(ap + 1, acc.y);
        atomicAdd(ap + 2, acc.z); atomicAdd(ap + 3, acc.w);
    }
}

// ---------------- conv combine + BN stats ----------------
__global__ void k_bn1(const float* __restrict__ root, const float* __restrict__ cb) {
    __shared__ float hs[4][DD];
    __shared__ float ms[4][DD];
    int tx = threadIdx.x, ty = threadIdx.y;
    int n = blockIdx.x * 4 + ty;
    hs[ty][tx] = g_h[n * DD + tx];
    __syncthreads();
    float c = g_cnt[n];
    float acc = g_agg[n * DD + tx] / fmaxf(c, 1.f) + cb[tx];
#pragma unroll
    for (int d = 0; d < DD; ++d) acc += hs[ty][d] * root[d * DD + tx];
    g_m[n * DD + tx] = acc;
    ms[ty][tx] = acc;
    __syncthreads();
    if (ty == 0) {
        float s  = ms[0][tx] + ms[1][tx] + ms[2][tx] + ms[3][tx];
        float sq = ms[0][tx] * ms[0][tx] + ms[1][tx] * ms[1][tx] +
                   ms[2][tx] * ms[2][tx] + ms[3][tx] * ms[3][tx];
        atomicAdd(&g_bnsum[tx], (double)s);
        atomicAdd(&g_bnsq[tx], (double)sq);
    }
}

__global__ void k_bnfin() {
    int o = threadIdx.x;
    double mu = g_bnsum[o] / (double)NN;
    double var = g_bnsq[o] / (double)NN - mu * mu;
    g_mu[o] = (float)mu;
    g_rstd[o] = rsqrtf((float)var + 1e-5f);
}

// ---------------- BN-apply + relu + GRU, 4 nodes/thread (isolated test) ----------------
__global__ void __launch_bounds__(256) k_gru(const float* __restrict__ gamma,
                                             const float* __restrict__ beta,
                                             const float* __restrict__ bih,
                                             const float* __restrict__ bhh) {
    __shared__ float ms[16][DD];
    __shared__ float hs[16][DD];
    int tx = threadIdx.x, ty = threadIdx.y;
    int tid = ty * 64 + tx;
    int nb = blockIdx.x * 16;
    for (int t = tid; t < 1024; t += 256) {
        int i = t >> 6, d = t & 63;
        int n = nb + i;
        float mv = g_m[n * DD + d];
        mv = gamma[d] * (mv - g_mu[d]) * g_rstd[d] + beta[d];
        ms[i][d] = fmaxf(mv, 0.f);
        hs[i][d] = g_h[n * DD + d];
    }
    __syncthreads();
    float gr[4], gz[4], gn[4], hr[4], hz[4], hn[4];
    float b0 = bih[tx], b1 = bih[DD + tx], b2 = bih[2 * DD + tx];
    float c0 = bhh[tx], c1 = bhh[DD + tx], c2 = bhh[2 * DD + tx];
#pragma unroll
    for (int r = 0; r < 4; r++) {
        gr[r] = b0; gz[r] = b1; gn[r] = b2;
        hr[r] = c0; hz[r] = c1; hn[r] = c2;
    }
    int i0 = ty * 4;
#pragma unroll 4
    for (int d = 0; d < DD; ++d) {
        const float* wT = g_wihT + d * 192;
        const float* vT = g_whhT + d * 192;
        float w0 = wT[tx], w1 = wT[64 + tx], w2 = wT[128 + tx];
        float v0 = vT[tx], v1 = vT[64 + tx], v2 = vT[128 + tx];
#pragma unroll
        for (int r = 0; r < 4; r++) {
            float md = ms[i0 + r][d], hd = hs[i0 + r][d];
            gr[r] += md * w0; gz[r] += md * w1; gn[r] += md * w2;
            hr[r] += hd * v0; hz[r] += hd * v1; hn[r] += hd * v2;
        }
    }
#pragma unroll
    for (int r = 0; r < 4; r++) {
        int n = nb + i0 + r;
        float hvv = hs[i0 + r][tx];
        float rr = 1.f / (1.f + __expf(-(gr[r] + hr[r])));
        float zz = 1.f / (1.f + __expf(-(gz[r] + hz[r])));
        float nn2 = tanhf(gn[r] + rr * hn[r]);
        g_h[n * DD + tx] = (1.f - zz) * nn2 + zz * hvv;
    }
}

// ---------------- pooling + head ----------------
__global__ void k_pool(const int* __restrict__ batch) {
    int i = blockIdx.x * blockDim.x + threadIdx.x;
    if (i >= NN * DD) return;
    int n = i >> 6, o = i & 63;
    atomicAdd(&g_pool[batch[n] * DD + o], g_h[i]);
}

__global__ void k_head(const float* __restrict__ pw, const float* __restrict__ pb,
                       const float* __restrict__ ow, const float* __restrict__ ob,
                       float* __restrict__ out) {
    __shared__ float p[DD];
    __shared__ float q[DD];
    int g = blockIdx.x, o = threadIdx.x;
    p[o] = g_pool[g * DD + o] / fmaxf(g_pcnt[g], 1.f);
    __syncthreads();
    float acc = pb[o];
#pragma unroll
    for (int d = 0; d < DD; ++d) acc += p[d] * pw[d * DD + o];
    q[o] = fmaxf(acc, 0.f) * ow[o];
    __syncthreads();
    if (o == 0) {
        float s = ob[0];
        for (int d = 0; d < DD; ++d) s += q[d];
        out[g] = s;
    }
}

// ---------------- launch ----------------
extern "C" void kernel_launch(void* const* d_in, const int* in_sizes, int n_in,
                              void* d_out, int out_size) {
    const float* x     = (const float*)d_in[0];
    const int*   ei    = (const int*)d_in[1];
    const float* ea    = (const float*)d_in[2];
    const int*   batch = (const int*)d_in[3];
    const float* pre_w = (const float*)d_in[4];
    const float* pre_b = (const float*)d_in[5];
    const float* ew1   = (const float*)d_in[6];
    const float* eb1   = (const float*)d_in[7];
    const float* ew2   = (const float*)d_in[8];
    const float* eb2   = (const float*)d_in[9];
    const float* root  = (const float*)d_in[10];
    const float* cb    = (const float*)d_in[11];
    const float* bng   = (const float*)d_in[12];
    const float* bnb   = (const float*)d_in[13];
    const float* wih   = (const float*)d_in[14];
    const float* whh   = (const float*)d_in[15];
    const float* bih   = (const float*)d_in[16];
    const float* bhh   = (const float*)d_in[17];
    const float* pw    = (const float*)d_in[18];
    const float* pb    = (const float*)d_in[19];
    const float* ow    = (const float*)d_in[20];
    const float* ob    = (const float*)d_in[21];
    float* out = (float*)d_out;
    const int* src = ei;
    const int* dst = ei + EE;

    // ncu captures the 4th launch (index 3): keep layer-0 k_ygemm there (control).
    k_pre<<<NN / 4, dim3(64, 4)>>>(x, pre_w, pre_b);                   // 0
    k_prep<<<(PREP_TOT + 255) / 256, 256>>>(ew2, eb2, wih, whh);       // 1 (layer 0)
    k_init<<<(NN + 255) / 256, 256>>>();                               // 2
    k_ygemm<<<dim3((NN + 63) / 64, (YW + 255) / 256), 256>>>();        // 3 (layer 0) <- profiled
    k_deg<<<(EE + 255) / 256, 256>>>(src, dst, batch);                 // 4
    k_scan<<<1, 1024>>>();                                             // 5
    k_perm<<<(EE + 255) / 256, 256>>>(src);                            // 6
    k_hid<<<EE / 4, dim3(64, 4)>>>(ea, ew1, eb1);                      // 7 (layer 0)

    for (int l = 0; l < LL; l++) {
        if (l > 0) {
            k_prep<<<(PREP_TOT + 255) / 256, 256>>>(ew2 + (size_t)l * DD * DD * DD,
                                                    eb2 + (size_t)l * DD * DD,
                                                    wih + (size_t)l * 3 * DD * DD,
                                                    whh + (size_t)l * 3 * DD * DD);
            k_hid<<<EE / 4, dim3(64, 4)>>>(ea, ew1 + (size_t)l * FEF * DD, eb1 + l * DD);
            k_ygemm<<<dim3((NN + 63) / 64, (YW + 255) / 256), 256>>>();
        }
        k_edge<<<EE / 32, 256>>>(src, dst);
        k_bn1<<<NN / 4, dim3(64, 4)>>>(root + (size_t)l * DD * DD, cb + l * DD);
        k_bnfin<<<1, 64>>>();
        k_gru<<<NN / 16, dim3(64, 4)>>>(bng + l * DD, bnb + l * DD,
                                        bih + (size_t)l * 3 * DD,
                                        bhh + (size_t)l * 3 * DD);
    }

    k_pool<<<(NN * DD + 255) / 256, 256>>>(batch);
    k_head<<<GG, 64>>>(pw, pb, ow, ob, out);
}

// round 15
// speedup vs baseline: 1.1811x; 1.0002x over previous
#include <cuda_runtime.h>

#define NN 20000
#define EE 100000
#define FNF 92
#define FEF 50
#define DD 64
#define GG 128
#define LL 3
#define YW 4160    // 64*64 + 64 bias cols (Y row stride, logical)
#define W2W 4352   // w2t row stride, padded so B tile loads never go OOB

// ---------------- device scratch (static; no runtime allocation) ----------------
__device__ float  g_h[NN * DD];
__device__ float  g_hid[(size_t)EE * DD];
__device__ float  g_agg[NN * DD];
__device__ float  g_m[NN * DD];
__device__ float  g_cnt[NN];
__device__ double g_bnsum[DD];
__device__ double g_bnsq[DD];
__device__ float  g_pool[GG * DD];
__device__ float  g_pcnt[GG];
__device__ float  g_Y[(size_t)NN * YW];
__device__ float  g_w2t[64 * W2W];
__device__ float  g_wihT[DD * 192];   // [d][gate*64 + out]
__device__ float  g_whhT[DD * 192];
__device__ int    g_deg[NN];
__device__ int    g_off[NN];
__device__ int    g_rank[EE];
__device__ int    g_eorder[EE];

// ---------------- init / CSR build ----------------
__global__ void k_init() {
    int i = blockIdx.x * blockDim.x + threadIdx.x;
    if (i < NN) { g_cnt[i] = 0.f; g_deg[i] = 0; }
    if (i < GG * DD) g_pool[i] = 0.f;
    if (i < GG) g_pcnt[i] = 0.f;
}

__global__ void k_deg(const int* __restrict__ src, const int* __restrict__ dst,
                      const int* __restrict__ batch) {
    int i = blockIdx.x * blockDim.x + threadIdx.x;
    if (i < EE) {
        g_rank[i] = atomicAdd(&g_deg[src[i]], 1);
        atomicAdd(&g_cnt[dst[i]], 1.f);
    }
    if (i < NN) atomicAdd(&g_pcnt[batch[i]], 1.f);
}

__global__ void k_scan() {
    __shared__ int s[1024];
    __shared__ int carry;
    int tid = threadIdx.x;
    if (tid == 0) carry = 0;
    __syncthreads();
    for (int base = 0; base < NN; base += 1024) {
        int v = (base + tid < NN) ? g_deg[base + tid] : 0;
        s[tid] = v;
        __syncthreads();
        for (int off = 1; off < 1024; off <<= 1) {
            int t = (tid >= off) ? s[tid - off] : 0;
            __syncthreads();
            s[tid] += t;
            __syncthreads();
        }
        if (base + tid < NN) g_off[base + tid] = carry + s[tid] - v;
        __syncthreads();
        if (tid == 0) carry += s[1023];
        __syncthreads();
    }
}

__global__ void k_perm(const int* __restrict__ src) {
    int e = blockIdx.x * blockDim.x + threadIdx.x;
    if (e < EE) g_eorder[g_off[src[e]] + g_rank[e]] = e;
}

// ---------------- per-layer prep: zero agg/bn + W2 transpose + GRU W transpose ----------------
#define PREP_ZL   (NN * DD)
#define PREP_W2T  (64 * W2W)
#define PREP_WTR  (DD * 192)
#define PREP_TOT  (PREP_ZL + PREP_W2T + PREP_WTR)
__global__ void k_prep(const float* __restrict__ W2, const float* __restrict__ b2,
                       const float* __restrict__ wih, const float* __restrict__ whh) {
    int i = blockIdx.x * blockDim.x + threadIdx.x;
    if (i < DD) { g_bnsum[i] = 0.0; g_bnsq[i] = 0.0; }
    if (i < PREP_ZL) {
        g_agg[i] = 0.f;
    } else if (i < PREP_ZL + PREP_W2T) {
        int t = i - PREP_ZL;
        int r = t / W2W, col = t % W2W;
        float v;
        if (col < 4096) {
            int j = col >> 6, o = col & 63;
            v = W2[j * 4096 + r * 64 + o];
        } else if (col < YW) {
            v = b2[r * 64 + (col - 4096)];
        } else {
            v = 0.f;   // read-side pad, never stored to Y
        }
        g_w2t[t] = v;
    } else if (i < PREP_TOT) {
        int t = i - PREP_ZL - PREP_W2T;
        int d = t / 192, k = t % 192;
        g_wihT[t] = wih[k * DD + d];
        g_whhT[t] = whh[k * DD + d];
    }
}

// ---------------- pre-FC ----------------
__global__ void k_pre(const float* __restrict__ x, const float* __restrict__ w,
                      const float* __restrict__ b) {
    __shared__ float xs[4][FNF];
    int tx = threadIdx.x, ty = threadIdx.y;
    int n = blockIdx.x * 4 + ty;
    for (int f = tx; f < FNF; f += 64) xs[ty][f] = x[(size_t)n * FNF + f];
    __syncthreads();
    float acc = b[tx];
#pragma unroll
    for (int f = 0; f < FNF; ++f) acc += xs[ty][f] * w[f * DD + tx];
    g_h[n * DD + tx] = fmaxf(acc, 0.f);
}

// ---------------- edge MLP stage 1 ----------------
__global__ void k_hid(const float* __restrict__ ea, const float* __restrict__ w,
                      const float* __restrict__ b) {
    __shared__ float es[4][FEF];
    int tx = threadIdx.x, ty = threadIdx.y;
    int e = blockIdx.x * 4 + ty;
    for (int f = tx; f < FEF; f += 64) es[ty][f] = ea[(size_t)e * FEF + f];
    __syncthreads();
    float acc = b[tx];
#pragma unroll
    for (int f = 0; f < FEF; ++f) acc += es[ty][f] * w[f * DD + tx];
    g_hid[(size_t)e * DD + tx] = fmaxf(acc, 0.f);
}

// ---------------- Y GEMM: g_Y = g_h @ g_w2t, B staged via smem (R11 version) ----------------
__global__ void __launch_bounds__(256, 2) k_ygemm() {
    __shared__ __align__(16) float hsT[64][68];
    __shared__ __align__(16) float Bs[16][256];
    int tid = threadIdx.x;
    int mb = blockIdx.x * 64;
    int nb = blockIdx.y * 256;

    for (int t = tid; t < 1024; t += 256) {
        int m = t >> 4, q = t & 15;
        int gm = mb + m;
        float4 v = make_float4(0.f, 0.f, 0.f, 0.f);
        if (gm < NN) v = *(const float4*)&g_h[gm * DD + q * 4];
        hsT[q * 4 + 0][m] = v.x; hsT[q * 4 + 1][m] = v.y;
        hsT[q * 4 + 2][m] = v.z; hsT[q * 4 + 3][m] = v.w;
    }

    int mg = tid >> 5, ng = tid & 31;
    int m0 = mg * 8;
    int nl0 = (ng & 15) * 4 + (ng >> 4) * 128;

    int bf_row[4], bf_col[4];
#pragma unroll
    for (int i = 0; i < 4; i++) {
        int f4 = tid + i * 256;
        bf_row[i] = f4 >> 6;
        bf_col[i] = (f4 & 63) * 4;
    }

    float4 pre[4];
#pragma unroll
    for (int i = 0; i < 4; i++)
        pre[i] = *(const float4*)&g_w2t[(size_t)bf_row[i] * W2W + nb + bf_col[i]];
#pragma unroll
    for (int i = 0; i < 4; i++)
        *(float4*)&Bs[bf_row[i]][bf_col[i]] = pre[i];
    __syncthreads();

    float acc[8][8];
#pragma unroll
    for (int a = 0; a < 8; a++)
#pragma unroll
        for (int b = 0; b < 8; b++) acc[a][b] = 0.f;

#pragma unroll
    for (int c = 0; c < 4; c++) {
        if (c < 3) {
#pragma unroll
            for (int i = 0; i < 4; i++)
                pre[i] = *(const float4*)&g_w2t[(size_t)((c + 1) * 16 + bf_row[i]) * W2W + nb + bf_col[i]];
        }
#pragma unroll
        for (int kk = 0; kk < 16; kk++) {
            int k = c * 16 + kk;
            float4 a0 = *(const float4*)&hsT[k][m0];
            float4 a1 = *(const float4*)&hsT[k][m0 + 4];
            float4 b0 = *(const float4*)&Bs[kk][nl0];
            float4 b1 = *(const float4*)&Bs[kk][nl0 + 64];
            float av[8] = {a0.x, a0.y, a0.z, a0.w, a1.x, a1.y, a1.z, a1.w};
            float bv[8] = {b0.x, b0.y, b0.z, b0.w, b1.x, b1.y, b1.z, b1.w};
#pragma unroll
            for (int mm = 0; mm < 8; mm++)
#pragma unroll
                for (int nn = 0; nn < 8; nn++) acc[mm][nn] += av[mm] * bv[nn];
        }
        __syncthreads();
        if (c < 3) {
#pragma unroll
            for (int i = 0; i < 4; i++)
                *(float4*)&Bs[bf_row[i]][bf_col[i]] = pre[i];
            __syncthreads();
        }
    }

    bool v0 = (nb + nl0) < YW;
    bool v1 = (nb + nl0 + 64) < YW;
#pragma unroll
    for (int mm = 0; mm < 8; mm++) {
        int gm = mb + m0 + mm;
        if (gm >= NN) continue;
        float* Cp = g_Y + (size_t)gm * YW + nb + nl0;
        if (v0) *(float4*)Cp        = make_float4(acc[mm][0], acc[mm][1], acc[mm][2], acc[mm][3]);
        if (v1) *(float4*)(Cp + 64) = make_float4(acc[mm][4], acc[mm][5], acc[mm][6], acc[mm][7]);
    }
}

// ---------------- edge phase v3: warp per src node, Y row read once per node ----------------
// Warp = 16 o-lanes x 2 slot-groups; 8 edge-slots/pass in registers. Per j, one
// y float4 LDG (256B unique per warp) is reused across all 8 edges.
__global__ void __launch_bounds__(256) k_edge(const int* __restrict__ dst) {
    __shared__ __align__(16) float hid_s[8][8][68];  // [warp][slot][j], pad 68
    __shared__ int sdst[8][8];
    __shared__ int seo[8][8];
    int tid = threadIdx.x;
    int w = tid >> 5, lane = tid & 31;
    int n = blockIdx.x * 8 + w;
    int d = g_deg[n];
    if (d == 0) return;
    int d0 = g_off[n];
    const float* Yr = g_Y + (size_t)n * YW;

    int g = lane >> 4;            // slot group: 0 -> slots 0..3, 1 -> slots 4..7
    int o4 = (lane & 15) * 4;
    float4 bias = *(const float4*)&Yr[4096 + o4];

    for (int base = 0; base < d; base += 8) {
        int ne = min(8, d - base);
        if (lane < 8) {
            int eo = (lane < ne) ? g_eorder[d0 + base + lane] : -1;
            seo[w][lane] = eo;
            sdst[w][lane] = (eo >= 0) ? dst[eo] : -1;
        }
        __syncwarp();
        // stage hid for up to 8 edges: 128 float4 over 32 lanes
#pragma unroll
        for (int i = 0; i < 4; i++) {
            int t = lane + i * 32;
            int slot = t >> 4, q = t & 15;
            int eo = seo[w][slot];
            if (eo >= 0)
                *(float4*)&hid_s[w][slot][q * 4] =
                    *(const float4*)&g_hid[(size_t)eo * DD + q * 4];
        }
        __syncwarp();

        float4 acc[4];
#pragma unroll
        for (int s = 0; s < 4; s++) acc[s] = make_float4(0.f, 0.f, 0.f, 0.f);

#pragma unroll 4
        for (int j = 0; j < 64; j++) {
            float4 y = *(const float4*)&Yr[j * 64 + o4];
#pragma unroll
            for (int s = 0; s < 4; s++) {
                float hj = hid_s[w][g * 4 + s][j];
                acc[s].x += hj * y.x; acc[s].y += hj * y.y;
                acc[s].z += hj * y.z; acc[s].w += hj * y.w;
            }
        }
#pragma unroll
        for (int s = 0; s < 4; s++) {
            int dd = sdst[w][g * 4 + s];
            if (dd >= 0) {
                float* ap = &g_agg[dd * DD + o4];
                atomicAdd(ap + 0, acc[s].x + bias.x);
                atomicAdd(ap + 1, acc[s].y + bias.y);
                atomicAdd(ap + 2, acc[s].z + bias.z);
                atomicAdd(ap + 3, acc[s].w + bias.w);
            }
        }
        __syncwarp();
    }
}

// ---------------- conv combine + BN stats ----------------
__global__ void k_bn1(const float* __restrict__ root, const float* __restrict__ cb) {
    __shared__ float hs[4][DD];
    __shared__ float ms[4][DD];
    int tx = threadIdx.x, ty = threadIdx.y;
    int n = blockIdx.x * 4 + ty;
    hs[ty][tx] = g_h[n * DD + tx];
    __syncthreads();
    float c = g_cnt[n];
    float acc = g_agg[n * DD + tx] / fmaxf(c, 1.f) + cb[tx];
#pragma unroll
    for (int d = 0; d < DD; ++d) acc += hs[ty][d] * root[d * DD + tx];
    g_m[n * DD + tx] = acc;
    ms[ty][tx] = acc;
    __syncthreads();
    if (ty == 0) {
        float s  = ms[0][tx] + ms[1][tx] + ms[2][tx] + ms[3][tx];
        float sq = ms[0][tx] * ms[0][tx] + ms[1][tx] * ms[1][tx] +
                   ms[2][tx] * ms[2][tx] + ms[3][tx] * ms[3][tx];
        atomicAdd(&g_bnsum[tx], (double)s);
        atomicAdd(&g_bnsq[tx], (double)sq);
    }
}

// ---------------- BN-finalize + BN-apply + relu + GRU, 4 nodes/thread ----------------
__global__ void __launch_bounds__(256) k_gru(const float* __restrict__ gamma,
                                             const float* __restrict__ beta,
                                             const float* __restrict__ bih,
                                             const float* __restrict__ bhh) {
    __shared__ float ms[16][DD];
    __shared__ float hs[16][DD];
    int tx = threadIdx.x, ty = threadIdx.y;
    int tid = ty * 64 + tx;
    int nb = blockIdx.x * 16;
    // inline BN finalize for this thread's channel (d == tx for all staged elems)
    double muD = g_bnsum[tx] / (double)NN;
    double varD = g_bnsq[tx] / (double)NN - muD * muD;
    float mu = (float)muD;
    float rstd = rsqrtf((float)varD + 1e-5f);
    float ga = gamma[tx], be = beta[tx];
    for (int t = tid; t < 1024; t += 256) {
        int i = t >> 6;          // d == t & 63 == tx (stride 256 keeps tx fixed)
        int n = nb + i;
        float mv = g_m[n * DD + tx];
        mv = ga * (mv - mu) * rstd + be;
        ms[i][tx] = fmaxf(mv, 0.f);
        hs[i][tx] = g_h[n * DD + tx];
    }
    __syncthreads();
    float gr[4], gz[4], gn[4], hr[4], hz[4], hn[4];
    float b0 = bih[tx], b1 = bih[DD + tx], b2 = bih[2 * DD + tx];
    float c0 = bhh[tx], c1 = bhh[DD + tx], c2 = bhh[2 * DD + tx];
#pragma unroll
    for (int r = 0; r < 4; r++) {
        gr[r] = b0; gz[r] = b1; gn[r] = b2;
        hr[r] = c0; hz[r] = c1; hn[r] = c2;
    }
    int i0 = ty * 4;
#pragma unroll 4
    for (int d = 0; d < DD; ++d) {
        const float* wT = g_wihT + d * 192;
        const float* vT = g_whhT + d * 192;
        float w0 = wT[tx], w1 = wT[64 + tx], w2 = wT[128 + tx];
        float v0 = vT[tx], v1 = vT[64 + tx], v2 = vT[128 + tx];
#pragma unroll
        for (int r = 0; r < 4; r++) {
            float md = ms[i0 + r][d], hd = hs[i0 + r][d];
            gr[r] += md * w0; gz[r] += md * w1; gn[r] += md * w2;
            hr[r] += hd * v0; hz[r] += hd * v1; hn[r] += hd * v2;
        }
    }
#pragma unroll
    for (int r = 0; r < 4; r++) {
        int n = nb + i0 + r;
        float hvv = hs[i0 + r][tx];
        float rr = 1.f / (1.f + __expf(-(gr[r] + hr[r])));
        float zz = 1.f / (1.f + __expf(-(gz[r] + hz[r])));
        float nn2 = tanhf(gn[r] + rr * hn[r]);
        g_h[n * DD + tx] = (1.f - zz) * nn2 + zz * hvv;
    }
}

// ---------------- pooling + head ----------------
__global__ void k_pool(const int* __restrict__ batch) {
    int i = blockIdx.x * blockDim.x + threadIdx.x;
    if (i >= NN * DD) return;
    int n = i >> 6, o = i & 63;
    atomicAdd(&g_pool[batch[n] * DD + o], g_h[i]);
}

__global__ void k_head(const float* __restrict__ pw, const float* __restrict__ pb,
                       const float* __restrict__ ow, const float* __restrict__ ob,
                       float* __restrict__ out) {
    __shared__ float p[DD];
    __shared__ float q[DD];
    int g = blockIdx.x, o = threadIdx.x;
    p[o] = g_pool[g * DD + o] / fmaxf(g_pcnt[g], 1.f);
    __syncthreads();
    float acc = pb[o];
#pragma unroll
    for (int d = 0; d < DD; ++d) acc += p[d] * pw[d * DD + o];
    q[o] = fmaxf(acc, 0.f) * ow[o];
    __syncthreads();
    if (o == 0) {
        float s = ob[0];
        for (int d = 0; d < DD; ++d) s += q[d];
        out[g] = s;
    }
}

// ---------------- launch ----------------
extern "C" void kernel_launch(void* const* d_in, const int* in_sizes, int n_in,
                              void* d_out, int out_size) {
    const float* x     = (const float*)d_in[0];
    const int*   ei    = (const int*)d_in[1];
    const float* ea    = (const float*)d_in[2];
    const int*   batch = (const int*)d_in[3];
    const float* pre_w = (const float*)d_in[4];
    const float* pre_b = (const float*)d_in[5];
    const float* ew1   = (const float*)d_in[6];
    const float* eb1   = (const float*)d_in[7];
    const float* ew2   = (const float*)d_in[8];
    const float* eb2   = (const float*)d_in[9];
    const float* root  = (const float*)d_in[10];
    const float* cb    = (const float*)d_in[11];
    const float* bng   = (const float*)d_in[12];
    const float* bnb   = (const float*)d_in[13];
    const float* wih   = (const float*)d_in[14];
    const float* whh   = (const float*)d_in[15];
    const float* bih   = (const float*)d_in[16];
    const float* bhh   = (const float*)d_in[17];
    const float* pw    = (const float*)d_in[18];
    const float* pb    = (const float*)d_in[19];
    const float* ow    = (const float*)d_in[20];
    const float* ob    = (const float*)d_in[21];
    float* out = (float*)d_out;
    const int* src = ei;
    const int* dst = ei + EE;

    // ncu captures the 4th launch (index 3): keep layer-0 k_ygemm there (control).
    k_pre<<<NN / 4, dim3(64, 4)>>>(x, pre_w, pre_b);                   // 0
    k_prep<<<(PREP_TOT + 255) / 256, 256>>>(ew2, eb2, wih, whh);       // 1 (layer 0)
    k_init<<<(NN + 255) / 256, 256>>>();                               // 2
    k_ygemm<<<dim3((NN + 63) / 64, (YW + 255) / 256), 256>>>();        // 3 (layer 0) <- profiled
    k_deg<<<(EE + 255) / 256, 256>>>(src, dst, batch);                 // 4
    k_scan<<<1, 1024>>>();                                             // 5
    k_perm<<<(EE + 255) / 256, 256>>>(src);                            // 6
    k_hid<<<EE / 4, dim3(64, 4)>>>(ea, ew1, eb1);                      // 7 (layer 0)

    for (int l = 0; l < LL; l++) {
        if (l > 0) {
            k_prep<<<(PREP_TOT + 255) / 256, 256>>>(ew2 + (size_t)l * DD * DD * DD,
                                                    eb2 + (size_t)l * DD * DD,
                                                    wih + (size_t)l * 3 * DD * DD,
                                                    whh + (size_t)l * 3 * DD * DD);
            k_hid<<<EE / 4, dim3(64, 4)>>>(ea, ew1 + (size_t)l * FEF * DD, eb1 + l * DD);
            k_ygemm<<<dim3((NN + 63) / 64, (YW + 255) / 256), 256>>>();
        }
        k_edge<<<NN / 8, 256>>>(dst);
        k_bn1<<<NN / 4, dim3(64, 4)>>>(root + (size_t)l * DD * DD, cb + l * DD);
        k_gru<<<NN / 16, dim3(64, 4)>>>(bng + l * DD, bnb + l * DD,
                                        bih + (size_t)l * 3 * DD,
                                        bhh + (size_t)l * 3 * DD);
    }

    k_pool<<<(NN * DD + 255) / 256, 256>>>(batch);
    k_head<<<GG, 64>>>(pw, pb, ow, ob, out);
}